// round 15
// baseline (speedup 1.0000x reference)
#include <cuda_runtime.h>
#include <cuda_fp16.h>
#include <cstdint>

// ============================================================================
// Problem: B=8, N=1024, D=1024, H=16, dk=64
// out = (0.5*softmax(QK^T/8, key-masked) + 0.5*row_norm(adj)) @ V  -> @Wo + bo
// mma.sync m16n8k16 fp16, fp32 accumulate, ldmatrix fragments,
// B-operands row-major via ldmatrix.trans.
// R15: GEMM = exact R11 (proven best). Attention q-tile 128 (256 thr, 8 warps)
//      to halve K/V traffic and block count.
// ============================================================================

__device__ __half g_Q16[8u * 1024u * 1024u];
__device__ __half g_K16[8u * 1024u * 1024u];
__device__ __half g_V16[8u * 1024u * 1024u];
__device__ __half g_X16[8u * 1024u * 1024u];
__device__ __half g_in16[4u * 8u * 1024u * 1024u];  // q|k|v|adj fp16 row-major
__device__ __half g_W16[4u * 1024u * 1024u];        // Wq|Wk|Wv|Wo fp16 row-major
__device__ float  g_inv[8u * 1024u];

// ---------------------------------------------------------------------------
__device__ __forceinline__ uint32_t smem_to_u32(const void* p) {
    uint32_t a;
    asm("{ .reg .u64 t; cvta.to.shared.u64 t, %1; cvt.u32.u64 %0, t; }" : "=r"(a) : "l"(p));
    return a;
}
__device__ __forceinline__ void cp_async16(uint32_t s, const void* g) {
    asm volatile("cp.async.cg.shared.global [%0], [%1], 16;" :: "r"(s), "l"(g));
}
#define CP_COMMIT() asm volatile("cp.async.commit_group;" ::: "memory")
#define CP_WAIT(n)  asm volatile("cp.async.wait_group %0;" :: "n"(n) : "memory")

__device__ __forceinline__ void mma_fp16(float* c, const uint32_t* a, const uint32_t* b) {
    asm volatile(
        "mma.sync.aligned.m16n8k16.row.col.f32.f16.f16.f32 "
        "{%0,%1,%2,%3}, {%4,%5,%6,%7}, {%8,%9}, {%0,%1,%2,%3};"
        : "+f"(c[0]), "+f"(c[1]), "+f"(c[2]), "+f"(c[3])
        : "r"(a[0]), "r"(a[1]), "r"(a[2]), "r"(a[3]), "r"(b[0]), "r"(b[1]));
}
__device__ __forceinline__ void ldsm_x4(uint32_t* r, uint32_t addr) {
    asm volatile("ldmatrix.sync.aligned.m8n8.x4.shared.b16 {%0,%1,%2,%3}, [%4];"
        : "=r"(r[0]), "=r"(r[1]), "=r"(r[2]), "=r"(r[3]) : "r"(addr));
}
__device__ __forceinline__ void ldsm_x4t(uint32_t* r, uint32_t addr) {
    asm volatile("ldmatrix.sync.aligned.m8n8.x4.trans.shared.b16 {%0,%1,%2,%3}, [%4];"
        : "=r"(r[0]), "=r"(r[1]), "=r"(r[2]), "=r"(r[3]) : "r"(addr));
}
__device__ __forceinline__ uint32_t pack_h2(float lo, float hi) {
    __half2 h = __floats2half2_rn(lo, hi);
    return *(uint32_t*)&h;
}

// ---------------------------------------------------------------------------
// inputs (q,k,v,adj) fp32 -> fp16 row-major; grid (4096, 4)
// ---------------------------------------------------------------------------
__global__ __launch_bounds__(256) void cvt_in4(
    const float* __restrict__ q, const float* __restrict__ k,
    const float* __restrict__ v, const float* __restrict__ adj,
    __half* __restrict__ out)
{
    const float* src = (blockIdx.y == 0) ? q : (blockIdx.y == 1) ? k
                     : (blockIdx.y == 2) ? v : adj;
    size_t idx = (size_t)blockIdx.x * 256 + threadIdx.x;
    float4 a = ((const float4*)src)[idx * 2];
    float4 b = ((const float4*)src)[idx * 2 + 1];
    uint4 o;
    o.x = pack_h2(a.x, a.y); o.y = pack_h2(a.z, a.w);
    o.z = pack_h2(b.x, b.y); o.w = pack_h2(b.z, b.w);
    ((uint4*)(out + (size_t)blockIdx.y * 8u * 1024u * 1024u))[idx] = o;
}

// weights fp32 -> fp16 row-major; grid (512, 4)
__global__ __launch_bounds__(256) void cvt_w4(
    const float* __restrict__ w0, const float* __restrict__ w1,
    const float* __restrict__ w2, const float* __restrict__ w3,
    __half* __restrict__ out)
{
    const float* src = (blockIdx.y == 0) ? w0 : (blockIdx.y == 1) ? w1
                     : (blockIdx.y == 2) ? w2 : w3;
    size_t idx = (size_t)blockIdx.x * 256 + threadIdx.x;
    float4 a = ((const float4*)src)[idx * 2];
    float4 b = ((const float4*)src)[idx * 2 + 1];
    uint4 o;
    o.x = pack_h2(a.x, a.y); o.y = pack_h2(a.z, a.w);
    o.z = pack_h2(b.x, b.y); o.w = pack_h2(b.z, b.w);
    ((uint4*)(out + (size_t)blockIdx.y * 1024u * 1024u))[idx] = o;
}

// ---------------------------------------------------------------------------
// adjacency row-sum -> 1/(sum+eps); one warp per row (fp32 source)
// ---------------------------------------------------------------------------
__global__ __launch_bounds__(256) void rowsum_inv(
    const float* __restrict__ adj, float* __restrict__ inv)
{
    const int row = blockIdx.x * 8 + (threadIdx.x >> 5);
    const int lane = threadIdx.x & 31;
    const float4* a = (const float4*)(adj + (size_t)row * 1024);
    float s = 0.f;
#pragma unroll
    for (int i = 0; i < 8; i++) {
        float4 v = a[lane + i * 32];
        s += (v.x + v.y) + (v.z + v.w);
    }
#pragma unroll
    for (int o = 16; o > 0; o >>= 1) s += __shfl_xor_sync(0xffffffffu, s, o);
    if (lane == 0) inv[row] = 1.0f / (s + 1e-6f);
}

// ---------------------------------------------------------------------------
// fp16 GEMM (exact R11): C[M,1024] = A[M,1024] @ B[1024,1024], row-major fp16.
// 128 threads, 4 warps (2x2), block 128x128, warp 64x64, k-tile 64,
// 3-stage cp.async.
// cmode 0: C(fp16)=D+bias; 1: C(fp16)=0.5*inv*D+Xin; 2: C(fp32)=D+bias
// ---------------------------------------------------------------------------
#define PA 36
#define PB 68
#define A_TILE (128 * PA)
#define B_TILE (64 * PB)
#define STG_STRIDE (A_TILE + B_TILE)
#define NSTG 3
#define GEMM_SMEM (STG_STRIDE * NSTG * 4)   // 107520 bytes

struct GemmArgs {
    const __half* A[3];
    const __half* B[3];
    const float* bias[3];
    void* C[3];
    const float* inv;
    const __half* Xin;
    size_t sA, sB, sC;
    int nsel;
    int cmode;
};

__global__ __launch_bounds__(128, 2) void gemm_fp16(GemmArgs args)
{
    extern __shared__ uint32_t smw[];
    const uint32_t base_u = smem_to_u32(smw);

    const int tid = threadIdx.x;
    const int wid = tid >> 5, lane = tid & 31;
    const int wm = wid >> 1, wn = wid & 1;
    const int g = lane >> 2, t = lane & 3;

    const int sel = (args.nsel > 1) ? blockIdx.z : 0;
    const int z   = (args.nsel > 1) ? 0 : blockIdx.z;

    const __half* Ab = args.A[sel] + (size_t)z * args.sA + (size_t)(blockIdx.y * 128) * 1024;
    const __half* Bb = args.B[sel] + (size_t)z * args.sB + blockIdx.x * 128;

    const uint32_t aOff = (uint32_t)((wm * 64 + (lane & 15)) * PA + ((lane & 16) ? 4 : 0));
    const uint32_t bOff = (uint32_t)(((lane & 7) + ((lane & 8) ? 8 : 0)) * PB
                                     + wn * 32 + ((lane & 16) ? 4 : 0));

    float c[4][8][4];
#pragma unroll
    for (int i = 0; i < 4; i++)
#pragma unroll
        for (int j = 0; j < 8; j++)
#pragma unroll
            for (int q = 0; q < 4; q++) c[i][j][q] = 0.f;

    auto load_stage = [&](int kt, int stg) {
        const uint32_t as_u = base_u + (uint32_t)(stg * STG_STRIDE) * 4;
        const uint32_t bs_u = as_u + (uint32_t)A_TILE * 4;
#pragma unroll
        for (int i = 0; i < 8; i++) {
            int ch = tid + i * 128;
            int r = ch >> 3, cw = (ch & 7) * 4;
            cp_async16(as_u + (uint32_t)(r * PA + cw) * 4,
                       Ab + (size_t)r * 1024 + kt * 64 + cw * 2);
        }
#pragma unroll
        for (int i = 0; i < 8; i++) {
            int ch = tid + i * 128;
            int r = ch >> 4, cw = (ch & 15) * 4;
            cp_async16(bs_u + (uint32_t)(r * PB + cw) * 4,
                       Bb + (size_t)(kt * 64 + r) * 1024 + cw * 2);
        }
        CP_COMMIT();
    };

    load_stage(0, 0);
    load_stage(1, 1);

    int stg = 0;
    for (int kt = 0; kt < 16; kt++) {
        if (kt + 2 < 16) { load_stage(kt + 2, (kt + 2) % NSTG); CP_WAIT(2); }
        else if (kt + 1 < 16) { CP_WAIT(1); }
        else { CP_WAIT(0); }
        __syncthreads();

        const uint32_t as_u = base_u + (uint32_t)(stg * STG_STRIDE) * 4;
        const uint32_t bs_u = as_u + (uint32_t)A_TILE * 4;
#pragma unroll
        for (int ks = 0; ks < 4; ks++) {
            uint32_t af[4][4];
#pragma unroll
            for (int i = 0; i < 4; i++)
                ldsm_x4(af[i], as_u + (aOff + i * 16 * PA + ks * 8) * 4);
            uint32_t bf[8][2];
#pragma unroll
            for (int jj = 0; jj < 4; jj++) {
                uint32_t r4[4];
                ldsm_x4t(r4, bs_u + (bOff + ks * 16 * PB + jj * 8) * 4);
                bf[2 * jj][0] = r4[0]; bf[2 * jj][1] = r4[1];
                bf[2 * jj + 1][0] = r4[2]; bf[2 * jj + 1][1] = r4[3];
            }
#pragma unroll
            for (int i = 0; i < 4; i++)
#pragma unroll
                for (int j = 0; j < 8; j++)
                    mma_fp16(c[i][j], af[i], bf[j]);
        }
        __syncthreads();
        stg = (stg + 1) % NSTG;
    }

    // ---- epilogue ----
    const int colW = blockIdx.x * 128 + wn * 64;
    const float* bias = args.bias[sel];
    const int cmode = args.cmode;

#pragma unroll
    for (int i = 0; i < 4; i++) {
        const int row0 = blockIdx.y * 128 + wm * 64 + i * 16 + g;
        const int row1 = row0 + 8;
        if (cmode == 0) {
            __half2* C16 = (__half2*)args.C[sel];
#pragma unroll
            for (int j = 0; j < 8; j++) {
                const int col = colW + j * 8 + 2 * t;
                const float b0 = bias[col], b1 = bias[col + 1];
                C16[(size_t)row0 * 512 + (col >> 1)] =
                    __floats2half2_rn(c[i][j][0] + b0, c[i][j][1] + b1);
                C16[(size_t)row1 * 512 + (col >> 1)] =
                    __floats2half2_rn(c[i][j][2] + b0, c[i][j][3] + b1);
            }
        } else if (cmode == 1) {
            __half2* C16 = (__half2*)args.C[0] + (size_t)z * (args.sC >> 1);
            const __half2* X16 = (const __half2*)args.Xin + (size_t)z * (args.sC >> 1);
            const float s0 = 0.5f * args.inv[z * 1024 + row0];
            const float s1 = 0.5f * args.inv[z * 1024 + row1];
#pragma unroll
            for (int j = 0; j < 8; j++) {
                const int col = colW + j * 8 + 2 * t;
                float2 x0 = __half22float2(X16[(size_t)row0 * 512 + (col >> 1)]);
                float2 x1 = __half22float2(X16[(size_t)row1 * 512 + (col >> 1)]);
                C16[(size_t)row0 * 512 + (col >> 1)] =
                    __floats2half2_rn(s0 * c[i][j][0] + x0.x, s0 * c[i][j][1] + x0.y);
                C16[(size_t)row1 * 512 + (col >> 1)] =
                    __floats2half2_rn(s1 * c[i][j][2] + x1.x, s1 * c[i][j][3] + x1.y);
            }
        } else {
            float* Cf = (float*)args.C[0];
#pragma unroll
            for (int j = 0; j < 8; j++) {
                const int col = colW + j * 8 + 2 * t;
                const float b0 = bias[col], b1 = bias[col + 1];
                *(float2*)(Cf + (size_t)row0 * 1024 + col) =
                    make_float2(c[i][j][0] + b0, c[i][j][1] + b1);
                *(float2*)(Cf + (size_t)row1 * 1024 + col) =
                    make_float2(c[i][j][2] + b0, c[i][j][3] + b1);
            }
        }
    }
}

// ---------------------------------------------------------------------------
// fp16 flash attention half, q-tile 128, 256 threads (8 warps x 16 q-rows):
// X16[b,q,h*64+d] = fp16( 0.5 * softmax(QK^T/8, key-masked) @ V )
// Smem: Qs[128] | Ps[128] | Ks[64] | Vs[64], all pitch 36 words.
// Per-warp math identical to R11 (validated).
// ---------------------------------------------------------------------------
#define QP16 36
#define ATT_SMEM ((128 + 128 + 64 + 64) * QP16 * 4)   // 55296 bytes

__global__ __launch_bounds__(256) void attn_fp16(
    const __half* __restrict__ Q, const __half* __restrict__ K,
    const __half* __restrict__ V, const int* __restrict__ mask,
    __half* __restrict__ X)
{
    extern __shared__ uint32_t smu[];
    uint32_t* Qs = smu;                     // [128][QP16]
    uint32_t* Ps = smu + 128 * QP16;        // [128][QP16]
    uint32_t* Ks = smu + 256 * QP16;        // [64][QP16]
    uint32_t* Vs = smu + 320 * QP16;        // [64][QP16]
    __shared__ int msk[64];

    const uint32_t base_u = smem_to_u32(smu);
    const uint32_t Qs_u = base_u;
    const uint32_t Ps_u = base_u + 128 * QP16 * 4;
    const uint32_t Ks_u = base_u + 256 * QP16 * 4;
    const uint32_t Vs_u = base_u + 320 * QP16 * 4;

    const int tid = threadIdx.x;
    const int wid = tid >> 5, lane = tid & 31;
    const int g = lane >> 2, t = lane & 3;
    const int b = blockIdx.z, h = blockIdx.y;
    const int q0 = blockIdx.x * 128;

    const __half* Qb = Q + ((size_t)b * 1024 + q0) * 1024 + h * 64;
    const __half* Kb = K + (size_t)b * 1024 * 1024 + h * 64;
    const __half* Vb = V + (size_t)b * 1024 * 1024 + h * 64;
    const int* mb = mask + b * 1024;

    const uint32_t aOff = (uint32_t)((wid * 16 + (lane & 15)) * QP16 + ((lane & 16) ? 4 : 0));
    const uint32_t kOff = (uint32_t)(((lane & 7) + ((lane & 16) ? 8 : 0)) * QP16
                                     + ((lane & 8) ? 4 : 0));
    const uint32_t vOff = (uint32_t)(((lane & 7) + ((lane & 8) ? 8 : 0)) * QP16
                                     + ((lane & 16) ? 4 : 0));

    // Q tile: 128 rows x 32 words -> 1024 uint4, 4/thread
    for (int idx = tid; idx < 1024; idx += 256) {
        int r = idx >> 3, c = (idx & 7) * 4;
        *(uint4*)(Qs + r * QP16 + c) = *(const uint4*)(Qb + (size_t)r * 1024 + c * 2);
    }

    float m0 = -1e30f, m1 = -1e30f, l0 = 0.f, l1 = 0.f;
    float o[8][4];
#pragma unroll
    for (int j = 0; j < 8; j++)
#pragma unroll
        for (int q = 0; q < 4; q++) o[j][q] = 0.f;

    const int rowA = wid * 16 + g;

    for (int kb = 0; kb < 1024; kb += 64) {
        __syncthreads();
        // K/V tiles: 64 rows x 32 words each -> 512 uint4 each, 2/thread each
        for (int idx = tid; idx < 512; idx += 256) {
            int r = idx >> 3, c = (idx & 7) * 4;
            *(uint4*)(Ks + r * QP16 + c) =
                *(const uint4*)(Kb + (size_t)(kb + r) * 1024 + c * 2);
            *(uint4*)(Vs + r * QP16 + c) =
                *(const uint4*)(Vb + (size_t)(kb + r) * 1024 + c * 2);
        }
        if (tid < 64) msk[tid] = mb[kb + tid];
        __syncthreads();

        // ---- S = Q K^T ----
        float s[8][4];
#pragma unroll
        for (int j = 0; j < 8; j++)
#pragma unroll
            for (int q = 0; q < 4; q++) s[j][q] = 0.f;

#pragma unroll
        for (int ks = 0; ks < 4; ks++) {
            uint32_t a[4];
            ldsm_x4(a, Qs_u + (aOff + ks * 8) * 4);
#pragma unroll
            for (int jj = 0; jj < 4; jj++) {
                uint32_t r4[4];
                ldsm_x4(r4, Ks_u + (kOff + jj * 16 * QP16 + ks * 8) * 4);
                mma_fp16(s[2 * jj], a, r4);
                mma_fp16(s[2 * jj + 1], a, r4 + 2);
            }
        }

        // ---- scale + mask; online softmax ----
        float tm0 = -1e30f, tm1 = -1e30f;
#pragma unroll
        for (int j = 0; j < 8; j++) {
            const bool d0 = (msk[j * 8 + 2 * t] == 0);
            const bool d1 = (msk[j * 8 + 2 * t + 1] == 0);
            s[j][0] = d0 ? -1e12f : s[j][0] * 0.125f;
            s[j][1] = d1 ? -1e12f : s[j][1] * 0.125f;
            s[j][2] = d0 ? -1e12f : s[j][2] * 0.125f;
            s[j][3] = d1 ? -1e12f : s[j][3] * 0.125f;
            tm0 = fmaxf(tm0, fmaxf(s[j][0], s[j][1]));
            tm1 = fmaxf(tm1, fmaxf(s[j][2], s[j][3]));
        }
        tm0 = fmaxf(tm0, __shfl_xor_sync(0xffffffffu, tm0, 1));
        tm0 = fmaxf(tm0, __shfl_xor_sync(0xffffffffu, tm0, 2));
        tm1 = fmaxf(tm1, __shfl_xor_sync(0xffffffffu, tm1, 1));
        tm1 = fmaxf(tm1, __shfl_xor_sync(0xffffffffu, tm1, 2));

        const float mn0 = fmaxf(m0, tm0), mn1 = fmaxf(m1, tm1);
        const float al0 = __expf(m0 - mn0), al1 = __expf(m1 - mn1);
        m0 = mn0; m1 = mn1;

        float ts0 = 0.f, ts1 = 0.f;
#pragma unroll
        for (int j = 0; j < 8; j++) {
            s[j][0] = __expf(s[j][0] - mn0);
            s[j][1] = __expf(s[j][1] - mn0);
            s[j][2] = __expf(s[j][2] - mn1);
            s[j][3] = __expf(s[j][3] - mn1);
            ts0 += s[j][0] + s[j][1];
            ts1 += s[j][2] + s[j][3];
        }
        ts0 += __shfl_xor_sync(0xffffffffu, ts0, 1);
        ts0 += __shfl_xor_sync(0xffffffffu, ts0, 2);
        ts1 += __shfl_xor_sync(0xffffffffu, ts1, 1);
        ts1 += __shfl_xor_sync(0xffffffffu, ts1, 2);
        l0 = l0 * al0 + ts0;
        l1 = l1 * al1 + ts1;

#pragma unroll
        for (int j = 0; j < 8; j++) {
            o[j][0] *= al0; o[j][1] *= al0;
            o[j][2] *= al1; o[j][3] *= al1;
        }

        // ---- stage P (warp-private rows) ----
#pragma unroll
        for (int j = 0; j < 8; j++) {
            Ps[rowA * QP16 + j * 4 + t]       = pack_h2(s[j][0], s[j][1]);
            Ps[(rowA + 8) * QP16 + j * 4 + t] = pack_h2(s[j][2], s[j][3]);
        }
        __syncwarp();

        // ---- O += P V (V row-major via trans) ----
#pragma unroll
        for (int ks = 0; ks < 4; ks++) {
            uint32_t a[4];
            ldsm_x4(a, Ps_u + (aOff + ks * 8) * 4);
#pragma unroll
            for (int jj = 0; jj < 4; jj++) {
                uint32_t r4[4];
                ldsm_x4t(r4, Vs_u + (vOff + ks * 16 * QP16 + jj * 8) * 4);
                mma_fp16(o[2 * jj], a, r4);
                mma_fp16(o[2 * jj + 1], a, r4 + 2);
            }
        }
    }

    // ---- epilogue: X16 = fp16(0.5 * O / l) ----
    const float sc0 = 0.5f / l0, sc1 = 0.5f / l1;
    __half2* Xr0 = (__half2*)X + ((size_t)b * 1024 + q0 + rowA) * 512 + h * 32;
    __half2* Xr1 = Xr0 + (size_t)8 * 512;
#pragma unroll
    for (int j = 0; j < 8; j++) {
        Xr0[j * 4 + t] = __floats2half2_rn(o[j][0] * sc0, o[j][1] * sc0);
        Xr1[j * 4 + t] = __floats2half2_rn(o[j][2] * sc1, o[j][3] * sc1);
    }
}

// ---------------------------------------------------------------------------
extern "C" void kernel_launch(void* const* d_in, const int* in_sizes, int n_in,
                              void* d_out, int out_size)
{
    const float* query = (const float*)d_in[0];
    const float* key   = (const float*)d_in[1];
    const float* value = (const float*)d_in[2];
    const float* adj   = (const float*)d_in[3];
    const int*   mask  = (const int*)d_in[5];
    const float* Wq = (const float*)d_in[6];
    const float* bq = (const float*)d_in[7];
    const float* Wk = (const float*)d_in[8];
    const float* bk = (const float*)d_in[9];
    const float* Wv = (const float*)d_in[10];
    const float* bv = (const float*)d_in[11];
    const float* Wo = (const float*)d_in[12];
    const float* bo = (const float*)d_in[13];
    float* out = (float*)d_out;

    __half *pQ, *pK, *pV, *pX, *pIn, *pW;
    float *pInv;
    cudaGetSymbolAddress((void**)&pQ, g_Q16);
    cudaGetSymbolAddress((void**)&pK, g_K16);
    cudaGetSymbolAddress((void**)&pV, g_V16);
    cudaGetSymbolAddress((void**)&pX, g_X16);
    cudaGetSymbolAddress((void**)&pIn, g_in16);
    cudaGetSymbolAddress((void**)&pW, g_W16);
    cudaGetSymbolAddress((void**)&pInv, g_inv);

    const size_t M8 = 8u * 1024u * 1024u;
    const size_t M1 = 1024u * 1024u;

    cudaFuncSetAttribute(gemm_fp16, cudaFuncAttributeMaxDynamicSharedMemorySize, GEMM_SMEM);
    cudaFuncSetAttribute(attn_fp16, cudaFuncAttributeMaxDynamicSharedMemorySize, ATT_SMEM);

    // conversions + rowsum
    cvt_in4<<<dim3(4096, 4), 256>>>(query, key, value, adj, pIn);
    cvt_w4<<<dim3(512, 4), 256>>>(Wq, Wk, Wv, Wo, pW);
    rowsum_inv<<<1024, 256>>>(adj, pInv);

    // fused QKV projection (fp16 out)
    {
        GemmArgs a{};
        a.A[0] = pIn; a.A[1] = pIn + M8; a.A[2] = pIn + 2 * M8;
        a.B[0] = pW; a.B[1] = pW + M1; a.B[2] = pW + 2 * M1;
        a.bias[0] = bq; a.bias[1] = bk; a.bias[2] = bv;
        a.C[0] = pQ; a.C[1] = pK; a.C[2] = pV;
        a.inv = pInv; a.Xin = pX;
        a.sA = a.sB = a.sC = 0;
        a.nsel = 3; a.cmode = 0;
        gemm_fp16<<<dim3(8, 64, 3), 128, GEMM_SMEM>>>(a);
    }

    // attention half -> X16 (q-tile 128)
    attn_fp16<<<dim3(8, 16, 8), 256, ATT_SMEM>>>(pQ, pK, pV, mask, pX);

    // adjacency half: X16 = fp16(0.5*diag(inv)*(adj@V) + X16), batched
    {
        GemmArgs a{};
        a.A[0] = pIn + 3 * M8;
        a.B[0] = pV;
        a.bias[0] = bq;  // unused
        a.C[0] = pX;
        a.inv = pInv; a.Xin = pX;
        a.sA = M1; a.sB = M1; a.sC = M1;
        a.nsel = 1; a.cmode = 1;
        gemm_fp16<<<dim3(8, 8, 8), 128, GEMM_SMEM>>>(a);
    }

    // output projection (fp32 out + bias)
    {
        GemmArgs a{};
        a.A[0] = pX;
        a.B[0] = pW + 3 * M1;
        a.bias[0] = bo;
        a.C[0] = out;
        a.inv = pInv; a.Xin = pX;
        a.sA = a.sB = a.sC = 0;
        a.nsel = 1; a.cmode = 2;
        gemm_fp16<<<dim3(8, 64, 1), 128, GEMM_SMEM>>>(a);
    }
}

// round 16
// speedup vs baseline: 1.5108x; 1.5108x over previous
#include <cuda_runtime.h>
#include <cuda_fp16.h>
#include <cstdint>

// ============================================================================
// Problem: B=8, N=1024, D=1024, H=16, dk=64
// out = (0.5*softmax(QK^T/8, key-masked) + 0.5*row_norm(adj)) @ V  -> @Wo + bo
// mma.sync m16n8k16 fp16, fp32 accumulate, ldmatrix fragments,
// B-operands row-major via ldmatrix.trans.
// R16: exact R11 configuration (best verified) + higher-ILP input conversion.
// ============================================================================

__device__ __half g_Q16[8u * 1024u * 1024u];
__device__ __half g_K16[8u * 1024u * 1024u];
__device__ __half g_V16[8u * 1024u * 1024u];
__device__ __half g_X16[8u * 1024u * 1024u];
__device__ __half g_in16[4u * 8u * 1024u * 1024u];  // q|k|v|adj fp16 row-major
__device__ __half g_W16[4u * 1024u * 1024u];        // Wq|Wk|Wv|Wo fp16 row-major
__device__ float  g_inv[8u * 1024u];

// ---------------------------------------------------------------------------
__device__ __forceinline__ uint32_t smem_to_u32(const void* p) {
    uint32_t a;
    asm("{ .reg .u64 t; cvta.to.shared.u64 t, %1; cvt.u32.u64 %0, t; }" : "=r"(a) : "l"(p));
    return a;
}
__device__ __forceinline__ void cp_async16(uint32_t s, const void* g) {
    asm volatile("cp.async.cg.shared.global [%0], [%1], 16;" :: "r"(s), "l"(g));
}
#define CP_COMMIT() asm volatile("cp.async.commit_group;" ::: "memory")
#define CP_WAIT(n)  asm volatile("cp.async.wait_group %0;" :: "n"(n) : "memory")

__device__ __forceinline__ void mma_fp16(float* c, const uint32_t* a, const uint32_t* b) {
    asm volatile(
        "mma.sync.aligned.m16n8k16.row.col.f32.f16.f16.f32 "
        "{%0,%1,%2,%3}, {%4,%5,%6,%7}, {%8,%9}, {%0,%1,%2,%3};"
        : "+f"(c[0]), "+f"(c[1]), "+f"(c[2]), "+f"(c[3])
        : "r"(a[0]), "r"(a[1]), "r"(a[2]), "r"(a[3]), "r"(b[0]), "r"(b[1]));
}
__device__ __forceinline__ void ldsm_x4(uint32_t* r, uint32_t addr) {
    asm volatile("ldmatrix.sync.aligned.m8n8.x4.shared.b16 {%0,%1,%2,%3}, [%4];"
        : "=r"(r[0]), "=r"(r[1]), "=r"(r[2]), "=r"(r[3]) : "r"(addr));
}
__device__ __forceinline__ void ldsm_x4t(uint32_t* r, uint32_t addr) {
    asm volatile("ldmatrix.sync.aligned.m8n8.x4.trans.shared.b16 {%0,%1,%2,%3}, [%4];"
        : "=r"(r[0]), "=r"(r[1]), "=r"(r[2]), "=r"(r[3]) : "r"(addr));
}
__device__ __forceinline__ uint32_t pack_h2(float lo, float hi) {
    __half2 h = __floats2half2_rn(lo, hi);
    return *(uint32_t*)&h;
}

// ---------------------------------------------------------------------------
// inputs (q,k,v,adj) fp32 -> fp16 row-major; grid (2048, 4), 16 elems/thread
// (4 independent float4 loads -> MLP 4, latency-bound kernel)
// ---------------------------------------------------------------------------
__global__ __launch_bounds__(256) void cvt_in4(
    const float* __restrict__ q, const float* __restrict__ k,
    const float* __restrict__ v, const float* __restrict__ adj,
    __half* __restrict__ out)
{
    const float* src = (blockIdx.y == 0) ? q : (blockIdx.y == 1) ? k
                     : (blockIdx.y == 2) ? v : adj;
    size_t idx = (size_t)blockIdx.x * 256 + threadIdx.x;   // 16-elem chunk id
    const float4* s4 = (const float4*)src + idx * 4;
    float4 a = s4[0];
    float4 b = s4[1];
    float4 c = s4[2];
    float4 d = s4[3];
    uint4 o0, o1;
    o0.x = pack_h2(a.x, a.y); o0.y = pack_h2(a.z, a.w);
    o0.z = pack_h2(b.x, b.y); o0.w = pack_h2(b.z, b.w);
    o1.x = pack_h2(c.x, c.y); o1.y = pack_h2(c.z, c.w);
    o1.z = pack_h2(d.x, d.y); o1.w = pack_h2(d.z, d.w);
    uint4* dst = (uint4*)(out + (size_t)blockIdx.y * 8u * 1024u * 1024u) + idx * 2;
    dst[0] = o0;
    dst[1] = o1;
}

// weights fp32 -> fp16 row-major; grid (512, 4)
__global__ __launch_bounds__(256) void cvt_w4(
    const float* __restrict__ w0, const float* __restrict__ w1,
    const float* __restrict__ w2, const float* __restrict__ w3,
    __half* __restrict__ out)
{
    const float* src = (blockIdx.y == 0) ? w0 : (blockIdx.y == 1) ? w1
                     : (blockIdx.y == 2) ? w2 : w3;
    size_t idx = (size_t)blockIdx.x * 256 + threadIdx.x;
    float4 a = ((const float4*)src)[idx * 2];
    float4 b = ((const float4*)src)[idx * 2 + 1];
    uint4 o;
    o.x = pack_h2(a.x, a.y); o.y = pack_h2(a.z, a.w);
    o.z = pack_h2(b.x, b.y); o.w = pack_h2(b.z, b.w);
    ((uint4*)(out + (size_t)blockIdx.y * 1024u * 1024u))[idx] = o;
}

// ---------------------------------------------------------------------------
// adjacency row-sum -> 1/(sum+eps); one warp per row (fp32 source)
// ---------------------------------------------------------------------------
__global__ __launch_bounds__(256) void rowsum_inv(
    const float* __restrict__ adj, float* __restrict__ inv)
{
    const int row = blockIdx.x * 8 + (threadIdx.x >> 5);
    const int lane = threadIdx.x & 31;
    const float4* a = (const float4*)(adj + (size_t)row * 1024);
    float s = 0.f;
#pragma unroll
    for (int i = 0; i < 8; i++) {
        float4 v = a[lane + i * 32];
        s += (v.x + v.y) + (v.z + v.w);
    }
#pragma unroll
    for (int o = 16; o > 0; o >>= 1) s += __shfl_xor_sync(0xffffffffu, s, o);
    if (lane == 0) inv[row] = 1.0f / (s + 1e-6f);
}

// ---------------------------------------------------------------------------
// fp16 GEMM (exact R11): C[M,1024] = A[M,1024] @ B[1024,1024], row-major fp16.
// 128 threads, 4 warps (2x2), block 128x128, warp 64x64, k-tile 64,
// 3-stage cp.async, 2 CTAs/SM.
// cmode 0: C(fp16)=D+bias; 1: C(fp16)=0.5*inv*D+Xin; 2: C(fp32)=D+bias
// ---------------------------------------------------------------------------
#define PA 36
#define PB 68
#define A_TILE (128 * PA)
#define B_TILE (64 * PB)
#define STG_STRIDE (A_TILE + B_TILE)
#define NSTG 3
#define GEMM_SMEM (STG_STRIDE * NSTG * 4)   // 107520 bytes

struct GemmArgs {
    const __half* A[3];
    const __half* B[3];
    const float* bias[3];
    void* C[3];
    const float* inv;
    const __half* Xin;
    size_t sA, sB, sC;
    int nsel;
    int cmode;
};

__global__ __launch_bounds__(128, 2) void gemm_fp16(GemmArgs args)
{
    extern __shared__ uint32_t smw[];
    const uint32_t base_u = smem_to_u32(smw);

    const int tid = threadIdx.x;
    const int wid = tid >> 5, lane = tid & 31;
    const int wm = wid >> 1, wn = wid & 1;
    const int g = lane >> 2, t = lane & 3;

    const int sel = (args.nsel > 1) ? blockIdx.z : 0;
    const int z   = (args.nsel > 1) ? 0 : blockIdx.z;

    const __half* Ab = args.A[sel] + (size_t)z * args.sA + (size_t)(blockIdx.y * 128) * 1024;
    const __half* Bb = args.B[sel] + (size_t)z * args.sB + blockIdx.x * 128;

    const uint32_t aOff = (uint32_t)((wm * 64 + (lane & 15)) * PA + ((lane & 16) ? 4 : 0));
    const uint32_t bOff = (uint32_t)(((lane & 7) + ((lane & 8) ? 8 : 0)) * PB
                                     + wn * 32 + ((lane & 16) ? 4 : 0));

    float c[4][8][4];
#pragma unroll
    for (int i = 0; i < 4; i++)
#pragma unroll
        for (int j = 0; j < 8; j++)
#pragma unroll
            for (int q = 0; q < 4; q++) c[i][j][q] = 0.f;

    auto load_stage = [&](int kt, int stg) {
        const uint32_t as_u = base_u + (uint32_t)(stg * STG_STRIDE) * 4;
        const uint32_t bs_u = as_u + (uint32_t)A_TILE * 4;
#pragma unroll
        for (int i = 0; i < 8; i++) {
            int ch = tid + i * 128;
            int r = ch >> 3, cw = (ch & 7) * 4;
            cp_async16(as_u + (uint32_t)(r * PA + cw) * 4,
                       Ab + (size_t)r * 1024 + kt * 64 + cw * 2);
        }
#pragma unroll
        for (int i = 0; i < 8; i++) {
            int ch = tid + i * 128;
            int r = ch >> 4, cw = (ch & 15) * 4;
            cp_async16(bs_u + (uint32_t)(r * PB + cw) * 4,
                       Bb + (size_t)(kt * 64 + r) * 1024 + cw * 2);
        }
        CP_COMMIT();
    };

    load_stage(0, 0);
    load_stage(1, 1);

    int stg = 0;
    for (int kt = 0; kt < 16; kt++) {
        if (kt + 2 < 16) { load_stage(kt + 2, (kt + 2) % NSTG); CP_WAIT(2); }
        else if (kt + 1 < 16) { CP_WAIT(1); }
        else { CP_WAIT(0); }
        __syncthreads();

        const uint32_t as_u = base_u + (uint32_t)(stg * STG_STRIDE) * 4;
        const uint32_t bs_u = as_u + (uint32_t)A_TILE * 4;
#pragma unroll
        for (int ks = 0; ks < 4; ks++) {
            uint32_t af[4][4];
#pragma unroll
            for (int i = 0; i < 4; i++)
                ldsm_x4(af[i], as_u + (aOff + i * 16 * PA + ks * 8) * 4);
            uint32_t bf[8][2];
#pragma unroll
            for (int jj = 0; jj < 4; jj++) {
                uint32_t r4[4];
                ldsm_x4t(r4, bs_u + (bOff + ks * 16 * PB + jj * 8) * 4);
                bf[2 * jj][0] = r4[0]; bf[2 * jj][1] = r4[1];
                bf[2 * jj + 1][0] = r4[2]; bf[2 * jj + 1][1] = r4[3];
            }
#pragma unroll
            for (int i = 0; i < 4; i++)
#pragma unroll
                for (int j = 0; j < 8; j++)
                    mma_fp16(c[i][j], af[i], bf[j]);
        }
        __syncthreads();
        stg = (stg + 1) % NSTG;
    }

    // ---- epilogue ----
    const int colW = blockIdx.x * 128 + wn * 64;
    const float* bias = args.bias[sel];
    const int cmode = args.cmode;

#pragma unroll
    for (int i = 0; i < 4; i++) {
        const int row0 = blockIdx.y * 128 + wm * 64 + i * 16 + g;
        const int row1 = row0 + 8;
        if (cmode == 0) {
            __half2* C16 = (__half2*)args.C[sel];
#pragma unroll
            for (int j = 0; j < 8; j++) {
                const int col = colW + j * 8 + 2 * t;
                const float b0 = bias[col], b1 = bias[col + 1];
                C16[(size_t)row0 * 512 + (col >> 1)] =
                    __floats2half2_rn(c[i][j][0] + b0, c[i][j][1] + b1);
                C16[(size_t)row1 * 512 + (col >> 1)] =
                    __floats2half2_rn(c[i][j][2] + b0, c[i][j][3] + b1);
            }
        } else if (cmode == 1) {
            __half2* C16 = (__half2*)args.C[0] + (size_t)z * (args.sC >> 1);
            const __half2* X16 = (const __half2*)args.Xin + (size_t)z * (args.sC >> 1);
            const float s0 = 0.5f * args.inv[z * 1024 + row0];
            const float s1 = 0.5f * args.inv[z * 1024 + row1];
#pragma unroll
            for (int j = 0; j < 8; j++) {
                const int col = colW + j * 8 + 2 * t;
                float2 x0 = __half22float2(X16[(size_t)row0 * 512 + (col >> 1)]);
                float2 x1 = __half22float2(X16[(size_t)row1 * 512 + (col >> 1)]);
                C16[(size_t)row0 * 512 + (col >> 1)] =
                    __floats2half2_rn(s0 * c[i][j][0] + x0.x, s0 * c[i][j][1] + x0.y);
                C16[(size_t)row1 * 512 + (col >> 1)] =
                    __floats2half2_rn(s1 * c[i][j][2] + x1.x, s1 * c[i][j][3] + x1.y);
            }
        } else {
            float* Cf = (float*)args.C[0];
#pragma unroll
            for (int j = 0; j < 8; j++) {
                const int col = colW + j * 8 + 2 * t;
                const float b0 = bias[col], b1 = bias[col + 1];
                *(float2*)(Cf + (size_t)row0 * 1024 + col) =
                    make_float2(c[i][j][0] + b0, c[i][j][1] + b1);
                *(float2*)(Cf + (size_t)row1 * 1024 + col) =
                    make_float2(c[i][j][2] + b0, c[i][j][3] + b1);
            }
        }
    }
}

// ---------------------------------------------------------------------------
// fp16 flash attention half (exact R11): q-tile 64, 128 threads, 4 warps.
// X16[b,q,h*64+d] = fp16( 0.5 * softmax(QK^T/8, key-masked) @ V )
// ---------------------------------------------------------------------------
#define QP16 36
#define ATT_SMEM (4 * 64 * QP16 * 4)   // 36864 bytes

__global__ __launch_bounds__(128) void attn_fp16(
    const __half* __restrict__ Q, const __half* __restrict__ K,
    const __half* __restrict__ V, const int* __restrict__ mask,
    __half* __restrict__ X)
{
    extern __shared__ uint32_t smu[];
    uint32_t* Qs = smu;
    uint32_t* Ks = smu + 64 * QP16;
    uint32_t* Ps = smu + 128 * QP16;
    uint32_t* Vs = smu + 192 * QP16;
    __shared__ int msk[64];

    const uint32_t base_u = smem_to_u32(smu);
    const uint32_t Qs_u = base_u;
    const uint32_t Ks_u = base_u + 64 * QP16 * 4;
    const uint32_t Ps_u = base_u + 128 * QP16 * 4;
    const uint32_t Vs_u = base_u + 192 * QP16 * 4;

    const int tid = threadIdx.x;
    const int wid = tid >> 5, lane = tid & 31;
    const int g = lane >> 2, t = lane & 3;
    const int b = blockIdx.z, h = blockIdx.y;
    const int q0 = blockIdx.x * 64;

    const __half* Qb = Q + ((size_t)b * 1024 + q0) * 1024 + h * 64;
    const __half* Kb = K + (size_t)b * 1024 * 1024 + h * 64;
    const __half* Vb = V + (size_t)b * 1024 * 1024 + h * 64;
    const int* mb = mask + b * 1024;

    const uint32_t aOff = (uint32_t)((wid * 16 + (lane & 15)) * QP16 + ((lane & 16) ? 4 : 0));
    const uint32_t kOff = (uint32_t)(((lane & 7) + ((lane & 16) ? 8 : 0)) * QP16
                                     + ((lane & 8) ? 4 : 0));
    const uint32_t vOff = (uint32_t)(((lane & 7) + ((lane & 8) ? 8 : 0)) * QP16
                                     + ((lane & 16) ? 4 : 0));

    for (int idx = tid; idx < 512; idx += 128) {
        int r = idx >> 3, c = (idx & 7) * 4;
        *(uint4*)(Qs + r * QP16 + c) = *(const uint4*)(Qb + (size_t)r * 1024 + c * 2);
    }

    float m0 = -1e30f, m1 = -1e30f, l0 = 0.f, l1 = 0.f;
    float o[8][4];
#pragma unroll
    for (int j = 0; j < 8; j++)
#pragma unroll
        for (int q = 0; q < 4; q++) o[j][q] = 0.f;

    const int rowA = wid * 16 + g;

    for (int kb = 0; kb < 1024; kb += 64) {
        __syncthreads();
        for (int idx = tid; idx < 512; idx += 128) {
            int r = idx >> 3, c = (idx & 7) * 4;
            *(uint4*)(Ks + r * QP16 + c) =
                *(const uint4*)(Kb + (size_t)(kb + r) * 1024 + c * 2);
            *(uint4*)(Vs + r * QP16 + c) =
                *(const uint4*)(Vb + (size_t)(kb + r) * 1024 + c * 2);
        }
        if (tid < 64) msk[tid] = mb[kb + tid];
        __syncthreads();

        float s[8][4];
#pragma unroll
        for (int j = 0; j < 8; j++)
#pragma unroll
            for (int q = 0; q < 4; q++) s[j][q] = 0.f;

#pragma unroll
        for (int ks = 0; ks < 4; ks++) {
            uint32_t a[4];
            ldsm_x4(a, Qs_u + (aOff + ks * 8) * 4);
#pragma unroll
            for (int jj = 0; jj < 4; jj++) {
                uint32_t r4[4];
                ldsm_x4(r4, Ks_u + (kOff + jj * 16 * QP16 + ks * 8) * 4);
                mma_fp16(s[2 * jj], a, r4);
                mma_fp16(s[2 * jj + 1], a, r4 + 2);
            }
        }

        float tm0 = -1e30f, tm1 = -1e30f;
#pragma unroll
        for (int j = 0; j < 8; j++) {
            const bool d0 = (msk[j * 8 + 2 * t] == 0);
            const bool d1 = (msk[j * 8 + 2 * t + 1] == 0);
            s[j][0] = d0 ? -1e12f : s[j][0] * 0.125f;
            s[j][1] = d1 ? -1e12f : s[j][1] * 0.125f;
            s[j][2] = d0 ? -1e12f : s[j][2] * 0.125f;
            s[j][3] = d1 ? -1e12f : s[j][3] * 0.125f;
            tm0 = fmaxf(tm0, fmaxf(s[j][0], s[j][1]));
            tm1 = fmaxf(tm1, fmaxf(s[j][2], s[j][3]));
        }
        tm0 = fmaxf(tm0, __shfl_xor_sync(0xffffffffu, tm0, 1));
        tm0 = fmaxf(tm0, __shfl_xor_sync(0xffffffffu, tm0, 2));
        tm1 = fmaxf(tm1, __shfl_xor_sync(0xffffffffu, tm1, 1));
        tm1 = fmaxf(tm1, __shfl_xor_sync(0xffffffffu, tm1, 2));

        const float mn0 = fmaxf(m0, tm0), mn1 = fmaxf(m1, tm1);
        const float al0 = __expf(m0 - mn0), al1 = __expf(m1 - mn1);
        m0 = mn0; m1 = mn1;

        float ts0 = 0.f, ts1 = 0.f;
#pragma unroll
        for (int j = 0; j < 8; j++) {
            s[j][0] = __expf(s[j][0] - mn0);
            s[j][1] = __expf(s[j][1] - mn0);
            s[j][2] = __expf(s[j][2] - mn1);
            s[j][3] = __expf(s[j][3] - mn1);
            ts0 += s[j][0] + s[j][1];
            ts1 += s[j][2] + s[j][3];
        }
        ts0 += __shfl_xor_sync(0xffffffffu, ts0, 1);
        ts0 += __shfl_xor_sync(0xffffffffu, ts0, 2);
        ts1 += __shfl_xor_sync(0xffffffffu, ts1, 1);
        ts1 += __shfl_xor_sync(0xffffffffu, ts1, 2);
        l0 = l0 * al0 + ts0;
        l1 = l1 * al1 + ts1;

#pragma unroll
        for (int j = 0; j < 8; j++) {
            o[j][0] *= al0; o[j][1] *= al0;
            o[j][2] *= al1; o[j][3] *= al1;
        }

#pragma unroll
        for (int j = 0; j < 8; j++) {
            Ps[rowA * QP16 + j * 4 + t]       = pack_h2(s[j][0], s[j][1]);
            Ps[(rowA + 8) * QP16 + j * 4 + t] = pack_h2(s[j][2], s[j][3]);
        }
        __syncwarp();

#pragma unroll
        for (int ks = 0; ks < 4; ks++) {
            uint32_t a[4];
            ldsm_x4(a, Ps_u + (aOff + ks * 8) * 4);
#pragma unroll
            for (int jj = 0; jj < 4; jj++) {
                uint32_t r4[4];
                ldsm_x4t(r4, Vs_u + (vOff + ks * 16 * QP16 + jj * 8) * 4);
                mma_fp16(o[2 * jj], a, r4);
                mma_fp16(o[2 * jj + 1], a, r4 + 2);
            }
        }
    }

    const float sc0 = 0.5f / l0, sc1 = 0.5f / l1;
    __half2* Xr0 = (__half2*)X + ((size_t)b * 1024 + q0 + rowA) * 512 + h * 32;
    __half2* Xr1 = Xr0 + (size_t)8 * 512;
#pragma unroll
    for (int j = 0; j < 8; j++) {
        Xr0[j * 4 + t] = __floats2half2_rn(o[j][0] * sc0, o[j][1] * sc0);
        Xr1[j * 4 + t] = __floats2half2_rn(o[j][2] * sc1, o[j][3] * sc1);
    }
}

// ---------------------------------------------------------------------------
extern "C" void kernel_launch(void* const* d_in, const int* in_sizes, int n_in,
                              void* d_out, int out_size)
{
    const float* query = (const float*)d_in[0];
    const float* key   = (const float*)d_in[1];
    const float* value = (const float*)d_in[2];
    const float* adj   = (const float*)d_in[3];
    const int*   mask  = (const int*)d_in[5];
    const float* Wq = (const float*)d_in[6];
    const float* bq = (const float*)d_in[7];
    const float* Wk = (const float*)d_in[8];
    const float* bk = (const float*)d_in[9];
    const float* Wv = (const float*)d_in[10];
    const float* bv = (const float*)d_in[11];
    const float* Wo = (const float*)d_in[12];
    const float* bo = (const float*)d_in[13];
    float* out = (float*)d_out;

    __half *pQ, *pK, *pV, *pX, *pIn, *pW;
    float *pInv;
    cudaGetSymbolAddress((void**)&pQ, g_Q16);
    cudaGetSymbolAddress((void**)&pK, g_K16);
    cudaGetSymbolAddress((void**)&pV, g_V16);
    cudaGetSymbolAddress((void**)&pX, g_X16);
    cudaGetSymbolAddress((void**)&pIn, g_in16);
    cudaGetSymbolAddress((void**)&pW, g_W16);
    cudaGetSymbolAddress((void**)&pInv, g_inv);

    const size_t M8 = 8u * 1024u * 1024u;
    const size_t M1 = 1024u * 1024u;

    cudaFuncSetAttribute(gemm_fp16, cudaFuncAttributeMaxDynamicSharedMemorySize, GEMM_SMEM);
    cudaFuncSetAttribute(attn_fp16, cudaFuncAttributeMaxDynamicSharedMemorySize, ATT_SMEM);

    // conversions + rowsum
    cvt_in4<<<dim3(2048, 4), 256>>>(query, key, value, adj, pIn);
    cvt_w4<<<dim3(512, 4), 256>>>(Wq, Wk, Wv, Wo, pW);
    rowsum_inv<<<1024, 256>>>(adj, pInv);

    // fused QKV projection (fp16 out)
    {
        GemmArgs a{};
        a.A[0] = pIn; a.A[1] = pIn + M8; a.A[2] = pIn + 2 * M8;
        a.B[0] = pW; a.B[1] = pW + M1; a.B[2] = pW + 2 * M1;
        a.bias[0] = bq; a.bias[1] = bk; a.bias[2] = bv;
        a.C[0] = pQ; a.C[1] = pK; a.C[2] = pV;
        a.inv = pInv; a.Xin = pX;
        a.sA = a.sB = a.sC = 0;
        a.nsel = 3; a.cmode = 0;
        gemm_fp16<<<dim3(8, 64, 3), 128, GEMM_SMEM>>>(a);
    }

    // attention half -> X16 (exact R11 shape)
    attn_fp16<<<dim3(16, 16, 8), 128, ATT_SMEM>>>(pQ, pK, pV, mask, pX);

    // adjacency half: X16 = fp16(0.5*diag(inv)*(adj@V) + X16), batched
    {
        GemmArgs a{};
        a.A[0] = pIn + 3 * M8;
        a.B[0] = pV;
        a.bias[0] = bq;  // unused
        a.C[0] = pX;
        a.inv = pInv; a.Xin = pX;
        a.sA = M1; a.sB = M1; a.sC = M1;
        a.nsel = 1; a.cmode = 1;
        gemm_fp16<<<dim3(8, 8, 8), 128, GEMM_SMEM>>>(a);
    }

    // output projection (fp32 out + bias)
    {
        GemmArgs a{};
        a.A[0] = pX;
        a.B[0] = pW + 3 * M1;
        a.bias[0] = bo;
        a.C[0] = out;
        a.inv = pInv; a.Xin = pX;
        a.sA = a.sB = a.sC = 0;
        a.nsel = 1; a.cmode = 2;
        gemm_fp16<<<dim3(8, 64, 1), 128, GEMM_SMEM>>>(a);
    }
}